// round 1
// baseline (speedup 1.0000x reference)
#include <cuda_runtime.h>
#include <math.h>

#define NB 64
#define TT 512
#define EE 512
#define KK 512
#define VV 512

// Scratch: static device globals (allocation-free per harness rules)
__device__ float g_Q [NB * TT * KK];
__device__ float g_Kp[NB * TT * KK];
__device__ float g_Vp[NB * TT * VV];
__device__ float g_S [NB * TT * TT];

// ---------------------------------------------------------------------------
// Fused projection GEMM: out = x @ W + b for W in {Wq,Wk,Wv} (blockIdx.z picks)
// M = NB*TT = 32768, N = 512, Kdim = 512. 128x128x16 tiles, 8x8 per thread.
// ---------------------------------------------------------------------------
__global__ __launch_bounds__(256) void proj_kernel(
    const float* __restrict__ x,
    const float* __restrict__ Wq, const float* __restrict__ bq,
    const float* __restrict__ Wk, const float* __restrict__ bk,
    const float* __restrict__ Wv, const float* __restrict__ bv)
{
    __shared__ float As[16][132];
    __shared__ float Bs[16][128];

    const int which = blockIdx.z;
    const float* __restrict__ W    = (which == 0) ? Wq : ((which == 1) ? Wk : Wv);
    const float* __restrict__ bias = (which == 0) ? bq : ((which == 1) ? bk : bv);
    float* out = (which == 0) ? g_Q : ((which == 1) ? g_Kp : g_Vp);

    const int rowBase = blockIdx.y * 128;
    const int colBase = blockIdx.x * 128;

    const int tid = threadIdx.x;
    const int tx = tid & 15;        // 0..15 -> output cols
    const int ty = tid >> 4;        // 0..15 -> output rows

    const int arow = tid >> 2;          // 0..63
    const int acol = (tid & 3) << 2;    // 0,4,8,12
    const int brow = tid >> 5;          // 0..7
    const int bcol = (tid & 31) << 2;   // 0..124

    const float* __restrict__ A  = x + (size_t)rowBase * EE;
    const float* __restrict__ Bm = W + colBase;

    float acc[8][8];
    #pragma unroll
    for (int i = 0; i < 8; ++i)
        #pragma unroll
        for (int j = 0; j < 8; ++j) acc[i][j] = 0.0f;

    for (int k0 = 0; k0 < EE; k0 += 16) {
        float4 a0 = *(const float4*)(A + (size_t)arow        * EE + k0 + acol);
        float4 a1 = *(const float4*)(A + (size_t)(arow + 64) * EE + k0 + acol);
        As[acol + 0][arow] = a0.x; As[acol + 1][arow] = a0.y;
        As[acol + 2][arow] = a0.z; As[acol + 3][arow] = a0.w;
        As[acol + 0][arow + 64] = a1.x; As[acol + 1][arow + 64] = a1.y;
        As[acol + 2][arow + 64] = a1.z; As[acol + 3][arow + 64] = a1.w;

        float4 b0 = *(const float4*)(Bm + (size_t)(k0 + brow)     * KK + bcol);
        float4 b1 = *(const float4*)(Bm + (size_t)(k0 + brow + 8) * KK + bcol);
        *(float4*)(&Bs[brow][bcol])     = b0;
        *(float4*)(&Bs[brow + 8][bcol]) = b1;
        __syncthreads();

        #pragma unroll
        for (int k = 0; k < 16; ++k) {
            float ra[8], rb[8];
            #pragma unroll
            for (int i = 0; i < 8; ++i) ra[i] = As[k][ty * 8 + i];
            #pragma unroll
            for (int j = 0; j < 8; ++j) rb[j] = Bs[k][tx * 8 + j];
            #pragma unroll
            for (int i = 0; i < 8; ++i)
                #pragma unroll
                for (int j = 0; j < 8; ++j)
                    acc[i][j] = fmaf(ra[i], rb[j], acc[i][j]);
        }
        __syncthreads();
    }

    float* C = out + (size_t)rowBase * KK + colBase;
    #pragma unroll
    for (int i = 0; i < 8; ++i) {
        #pragma unroll
        for (int j = 0; j < 8; ++j) {
            C[(size_t)(ty * 8 + i) * KK + tx * 8 + j] =
                acc[i][j] + bias[colBase + tx * 8 + j];
        }
    }
}

// ---------------------------------------------------------------------------
// Scores: S[b,t,s] = scale * dot(Q[b,t,:], K[b,s,:]) ; only tiles with
// sTile <= tTile are computed (upper-triangular tiles are never read).
// NT GEMM: both operands row-major, dot of rows.
// ---------------------------------------------------------------------------
__global__ __launch_bounds__(256) void qkt_kernel()
{
    const int sTile = blockIdx.x;
    const int tTile = blockIdx.y;
    const int b     = blockIdx.z;
    if (sTile > tTile) return;

    __shared__ float As[16][132];
    __shared__ float Bs[16][132];

    const float SCALE = 0.04419417382415922f;  // 1/sqrt(512)

    const int tid = threadIdx.x;
    const int tx = tid & 15;
    const int ty = tid >> 4;
    const int arow = tid >> 2;
    const int acol = (tid & 3) << 2;

    const float* __restrict__ Qp = g_Q  + (size_t)b * TT * KK + (size_t)tTile * 128 * KK;
    const float* __restrict__ Kq = g_Kp + (size_t)b * TT * KK + (size_t)sTile * 128 * KK;

    float acc[8][8];
    #pragma unroll
    for (int i = 0; i < 8; ++i)
        #pragma unroll
        for (int j = 0; j < 8; ++j) acc[i][j] = 0.0f;

    for (int k0 = 0; k0 < KK; k0 += 16) {
        float4 a0 = *(const float4*)(Qp + (size_t)arow        * KK + k0 + acol);
        float4 a1 = *(const float4*)(Qp + (size_t)(arow + 64) * KK + k0 + acol);
        As[acol + 0][arow] = a0.x; As[acol + 1][arow] = a0.y;
        As[acol + 2][arow] = a0.z; As[acol + 3][arow] = a0.w;
        As[acol + 0][arow + 64] = a1.x; As[acol + 1][arow + 64] = a1.y;
        As[acol + 2][arow + 64] = a1.z; As[acol + 3][arow + 64] = a1.w;

        float4 b0 = *(const float4*)(Kq + (size_t)arow        * KK + k0 + acol);
        float4 b1 = *(const float4*)(Kq + (size_t)(arow + 64) * KK + k0 + acol);
        Bs[acol + 0][arow] = b0.x; Bs[acol + 1][arow] = b0.y;
        Bs[acol + 2][arow] = b0.z; Bs[acol + 3][arow] = b0.w;
        Bs[acol + 0][arow + 64] = b1.x; Bs[acol + 1][arow + 64] = b1.y;
        Bs[acol + 2][arow + 64] = b1.z; Bs[acol + 3][arow + 64] = b1.w;
        __syncthreads();

        #pragma unroll
        for (int k = 0; k < 16; ++k) {
            float ra[8], rb[8];
            #pragma unroll
            for (int i = 0; i < 8; ++i) ra[i] = As[k][ty * 8 + i];
            #pragma unroll
            for (int j = 0; j < 8; ++j) rb[j] = Bs[k][tx * 8 + j];
            #pragma unroll
            for (int i = 0; i < 8; ++i)
                #pragma unroll
                for (int j = 0; j < 8; ++j)
                    acc[i][j] = fmaf(ra[i], rb[j], acc[i][j]);
        }
        __syncthreads();
    }

    float* Sp = g_S + (size_t)b * TT * TT + (size_t)(tTile * 128) * TT + sTile * 128;
    #pragma unroll
    for (int i = 0; i < 8; ++i) {
        #pragma unroll
        for (int j = 0; j < 8; ++j) {
            Sp[(size_t)(ty * 8 + i) * TT + tx * 8 + j] = acc[i][j] * SCALE;
        }
    }
}

// ---------------------------------------------------------------------------
// Column softmax (axis = query/t axis). One thread per column s.
// Valid entries are t >= s. Writes zeros for t < s inside the diagonal tile
// (the only above-diagonal entries the final GEMM ever reads).
// Warp reads 32 consecutive s at fixed t -> fully coalesced.
// ---------------------------------------------------------------------------
__global__ __launch_bounds__(128) void softmax_kernel()
{
    const int b = blockIdx.y;
    const int s = blockIdx.x * 128 + threadIdx.x;
    float* Sb = g_S + (size_t)b * TT * TT;

    const int tile0 = blockIdx.x * 128;
    const int w0    = tile0 + (threadIdx.x & ~31);  // warp-uniform start

    float m = -1e30f;
    #pragma unroll 4
    for (int t = w0; t < TT; ++t) {
        float xv = Sb[(size_t)t * TT + s];
        if (t >= s) m = fmaxf(m, xv);
    }
    float sum = 0.0f;
    #pragma unroll 4
    for (int t = w0; t < TT; ++t) {
        float xv = Sb[(size_t)t * TT + s];
        if (t >= s) sum += __expf(xv - m);
    }
    const float inv = 1.0f / sum;
    #pragma unroll 4
    for (int t = tile0; t < TT; ++t) {
        float xv = Sb[(size_t)t * TT + s];
        Sb[(size_t)t * TT + s] = (t >= s) ? __expf(xv - m) * inv : 0.0f;
    }
}

// ---------------------------------------------------------------------------
// out[b,t,v] = sum_s attn[b,t,s] * V[b,s,v]. attn is zero for s > t, so the
// k (=s) loop stops at the end of the diagonal tile: kEnd = (tTile+1)*128.
// NN GEMM.
// ---------------------------------------------------------------------------
__global__ __launch_bounds__(256) void av_kernel(float* __restrict__ out)
{
    const int vTile = blockIdx.x;
    const int tTile = blockIdx.y;
    const int b     = blockIdx.z;

    __shared__ float As[16][132];
    __shared__ float Bs[16][128];

    const int tid = threadIdx.x;
    const int tx = tid & 15;
    const int ty = tid >> 4;
    const int arow = tid >> 2;
    const int acol = (tid & 3) << 2;
    const int brow = tid >> 5;
    const int bcol = (tid & 31) << 2;

    const float* __restrict__ A  = g_S  + (size_t)b * TT * TT + (size_t)(tTile * 128) * TT;
    const float* __restrict__ Bm = g_Vp + (size_t)b * TT * VV + vTile * 128;
    const int kEnd = (tTile + 1) * 128;

    float acc[8][8];
    #pragma unroll
    for (int i = 0; i < 8; ++i)
        #pragma unroll
        for (int j = 0; j < 8; ++j) acc[i][j] = 0.0f;

    for (int k0 = 0; k0 < kEnd; k0 += 16) {
        float4 a0 = *(const float4*)(A + (size_t)arow        * TT + k0 + acol);
        float4 a1 = *(const float4*)(A + (size_t)(arow + 64) * TT + k0 + acol);
        As[acol + 0][arow] = a0.x; As[acol + 1][arow] = a0.y;
        As[acol + 2][arow] = a0.z; As[acol + 3][arow] = a0.w;
        As[acol + 0][arow + 64] = a1.x; As[acol + 1][arow + 64] = a1.y;
        As[acol + 2][arow + 64] = a1.z; As[acol + 3][arow + 64] = a1.w;

        float4 b0 = *(const float4*)(Bm + (size_t)(k0 + brow)     * VV + bcol);
        float4 b1 = *(const float4*)(Bm + (size_t)(k0 + brow + 8) * VV + bcol);
        *(float4*)(&Bs[brow][bcol])     = b0;
        *(float4*)(&Bs[brow + 8][bcol]) = b1;
        __syncthreads();

        #pragma unroll
        for (int k = 0; k < 16; ++k) {
            float ra[8], rb[8];
            #pragma unroll
            for (int i = 0; i < 8; ++i) ra[i] = As[k][ty * 8 + i];
            #pragma unroll
            for (int j = 0; j < 8; ++j) rb[j] = Bs[k][tx * 8 + j];
            #pragma unroll
            for (int i = 0; i < 8; ++i)
                #pragma unroll
                for (int j = 0; j < 8; ++j)
                    acc[i][j] = fmaf(ra[i], rb[j], acc[i][j]);
        }
        __syncthreads();
    }

    float* C = out + (size_t)b * TT * VV + (size_t)(tTile * 128) * VV + vTile * 128;
    #pragma unroll
    for (int i = 0; i < 8; ++i) {
        #pragma unroll
        for (int j = 0; j < 8; ++j) {
            C[(size_t)(ty * 8 + i) * VV + tx * 8 + j] = acc[i][j];
        }
    }
}

// ---------------------------------------------------------------------------
extern "C" void kernel_launch(void* const* d_in, const int* in_sizes, int n_in,
                              void* d_out, int out_size)
{
    const float* x  = (const float*)d_in[0];
    const float* Wq = (const float*)d_in[1];
    const float* bq = (const float*)d_in[2];
    const float* Wk = (const float*)d_in[3];
    const float* bk = (const float*)d_in[4];
    const float* Wv = (const float*)d_in[5];
    const float* bv = (const float*)d_in[6];
    float* out = (float*)d_out;

    proj_kernel   <<<dim3(4, 256, 3), 256>>>(x, Wq, bq, Wk, bk, Wv, bv);
    qkt_kernel    <<<dim3(4, 4, 64),  256>>>();
    softmax_kernel<<<dim3(4, 64),     128>>>();
    av_kernel     <<<dim3(4, 4, 64),  256>>>(out);
}

// round 3
// speedup vs baseline: 2.3744x; 2.3744x over previous
#include <cuda_runtime.h>
#include <cstdint>
#include <math.h>

#define NB 64
#define TT 512
#define EE 512
#define KK 512
#define VV 512
#define BK 16

// ---------------------------------------------------------------------------
// Device scratch (allocation-free per harness rules)
// ---------------------------------------------------------------------------
__device__ float g_x [(size_t)NB * TT * EE];   // tf32-rounded copy of x
__device__ float g_WT[(size_t)3 * EE * KK];    // W^T (N,K row-major), rounded
__device__ float g_Q [(size_t)NB * TT * KK];
__device__ float g_Kp[(size_t)NB * TT * KK];
__device__ float g_Vp[(size_t)NB * TT * VV];
__device__ float g_Vt[(size_t)NB * TT * VV];   // V^T per batch: [b][v][s]
__device__ float g_S [(size_t)NB * TT * TT];

// ---------------------------------------------------------------------------
// Helpers
// ---------------------------------------------------------------------------
__device__ __forceinline__ uint32_t smem_u32(const void* p) {
    uint32_t a;
    asm("{ .reg .u64 t; cvta.to.shared.u64 t, %1; cvt.u32.u64 %0, t; }"
        : "=r"(a) : "l"(p));
    return a;
}
__device__ __forceinline__ float rna_tf32(float x) {
    float r;
    asm("cvt.rna.tf32.f32 %0, %1;" : "=f"(r) : "f"(x));
    return r;
}

#define CP_ASYNC16(dst, src) \
    asm volatile("cp.async.cg.shared.global [%0], [%1], 16;" \
                 :: "r"(dst), "l"(src) : "memory")
#define CP_COMMIT() asm volatile("cp.async.commit_group;" ::: "memory")
#define CP_WAIT0()  asm volatile("cp.async.wait_group 0;" ::: "memory")
#define CP_WAIT1()  asm volatile("cp.async.wait_group 1;" ::: "memory")

// m16n8k8 tf32 MMA: D += A*B, A row-major fragment, B col-major fragment
__device__ __forceinline__ void mma_tf32(float* c, const uint32_t* a,
                                         const uint32_t* b) {
    asm volatile(
        "mma.sync.aligned.m16n8k8.row.col.f32.tf32.tf32.f32 "
        "{%0,%1,%2,%3}, {%4,%5,%6,%7}, {%8,%9}, {%0,%1,%2,%3};"
        : "+f"(c[0]), "+f"(c[1]), "+f"(c[2]), "+f"(c[3])
        : "r"(a[0]), "r"(a[1]), "r"(a[2]), "r"(a[3]), "r"(b[0]), "r"(b[1]));
}

// ---------------------------------------------------------------------------
// Shared tile storage: [128 rows][BK + 4 pad] -> conflict-free fragment loads
// ---------------------------------------------------------------------------
struct __align__(16) SmemT {
    float A[2][128][BK + 4];
    float B[2][128][BK + 4];
};   // 2*2*128*20*4 = 40960 bytes (static shared, <48KB)

// Fill one 128 x BK tile (rows contiguous in gmem, leading dim ldf floats)
__device__ __forceinline__ void load_tile(float (*dst)[BK + 4],
                                          const float* __restrict__ gsrc,
                                          int ldf, int tid) {
    unsigned long long gb = (unsigned long long)__cvta_generic_to_global(gsrc);
    #pragma unroll
    for (int i = 0; i < 2; ++i) {
        int ch  = i * 256 + tid;        // 0..511 chunks of 16B
        int row = ch >> 2;
        int off = ch & 3;
        uint32_t d = smem_u32(&dst[row][off * 4]);
        unsigned long long s = gb + (unsigned long long)row * ((size_t)ldf * 4)
                                  + (unsigned)off * 16;
        CP_ASYNC16(d, s);
    }
}

// One BK=16 chunk of MMAs for this warp (2 k8-steps x 4 m-tiles x 4 n-tiles)
__device__ __forceinline__ void compute_chunk(const float (*As)[BK + 4],
                                              const float (*Bs)[BK + 4],
                                              float c[4][4][4],
                                              int wr, int wc, int lane) {
    const int g = lane >> 2, q = lane & 3;
    #pragma unroll
    for (int k8 = 0; k8 < 2; ++k8) {
        const int k0 = k8 * 8;
        uint32_t a[4][4], b[4][2];
        #pragma unroll
        for (int mt = 0; mt < 4; ++mt) {
            const int r = wr * 64 + mt * 16 + g;
            a[mt][0] = __float_as_uint(As[r    ][k0 + q    ]);
            a[mt][1] = __float_as_uint(As[r + 8][k0 + q    ]);
            a[mt][2] = __float_as_uint(As[r    ][k0 + q + 4]);
            a[mt][3] = __float_as_uint(As[r + 8][k0 + q + 4]);
        }
        #pragma unroll
        for (int nt = 0; nt < 4; ++nt) {
            const int r = wc * 32 + nt * 8 + g;
            b[nt][0] = __float_as_uint(Bs[r][k0 + q    ]);
            b[nt][1] = __float_as_uint(Bs[r][k0 + q + 4]);
        }
        #pragma unroll
        for (int mt = 0; mt < 4; ++mt)
            #pragma unroll
            for (int nt = 0; nt < 4; ++nt)
                mma_tf32(c[mt][nt], a[mt], b[nt]);
    }
}

// Full mainloop: C128x128 += A[128,K] . B[128,K]^T over nc chunks of BK
__device__ __forceinline__ void gemm_mainloop(SmemT& sm,
                                              const float* __restrict__ A, int lda,
                                              const float* __restrict__ B, int ldb,
                                              int nc, int tid,
                                              float c[4][4][4],
                                              int wr, int wc, int lane) {
    load_tile(sm.A[0], A, lda, tid);
    load_tile(sm.B[0], B, ldb, tid);
    CP_COMMIT();

    for (int ch = 0; ch < nc; ++ch) {
        const int buf = ch & 1;
        if (ch + 1 < nc) {
            load_tile(sm.A[1 - buf], A + (size_t)(ch + 1) * BK, lda, tid);
            load_tile(sm.B[1 - buf], B + (size_t)(ch + 1) * BK, ldb, tid);
            CP_COMMIT();
            CP_WAIT1();
        } else {
            CP_WAIT0();
        }
        __syncthreads();
        compute_chunk(sm.A[buf], sm.B[buf], c, wr, wc, lane);
        __syncthreads();
    }
}

// Epilogue: write accumulators. mode 0: +bias & rna ; 1: *scale ; 2: rna ; 3: raw
__device__ __forceinline__ void gemm_epilogue(float c[4][4][4],
                                              float* __restrict__ Crow, int ldc,
                                              int colBase, int mode,
                                              const float* __restrict__ bias,
                                              int wr, int wc, int lane) {
    const float SCALE = 0.04419417382415922f;   // 1/sqrt(512)
    const int g = lane >> 2, q = lane & 3;
    #pragma unroll
    for (int mt = 0; mt < 4; ++mt) {
        #pragma unroll
        for (int nt = 0; nt < 4; ++nt) {
            const int row = wr * 64 + mt * 16 + g;
            const int col = colBase + wc * 32 + nt * 8 + q * 2;
            float v0 = c[mt][nt][0], v1 = c[mt][nt][1];
            float v2 = c[mt][nt][2], v3 = c[mt][nt][3];
            if (mode == 0) {
                float b0 = __ldg(bias + col), b1 = __ldg(bias + col + 1);
                v0 = rna_tf32(v0 + b0); v1 = rna_tf32(v1 + b1);
                v2 = rna_tf32(v2 + b0); v3 = rna_tf32(v3 + b1);
            } else if (mode == 1) {
                v0 *= SCALE; v1 *= SCALE; v2 *= SCALE; v3 *= SCALE;
            } else if (mode == 2) {
                v0 = rna_tf32(v0); v1 = rna_tf32(v1);
                v2 = rna_tf32(v2); v3 = rna_tf32(v3);
            }
            *(float2*)&Crow[(size_t)row * ldc + col]       = make_float2(v0, v1);
            *(float2*)&Crow[(size_t)(row + 8) * ldc + col] = make_float2(v2, v3);
        }
    }
}

// ---------------------------------------------------------------------------
// GEMM kernels
// ---------------------------------------------------------------------------
__global__ __launch_bounds__(256) void proj_mma(const float* __restrict__ bq,
                                                const float* __restrict__ bk,
                                                const float* __restrict__ bv) {
    __shared__ SmemT sm;
    const int tid = threadIdx.x, lane = tid & 31, wid = tid >> 5;
    const int wr = wid >> 2, wc = wid & 3;
    const int colT = blockIdx.x, rowT = blockIdx.y, which = blockIdx.z;

    const float* A = g_x + (size_t)rowT * 128 * EE;
    const float* B = g_WT + (size_t)which * EE * KK + (size_t)colT * 128 * EE;
    float* Cmat = (which == 0) ? g_Q : ((which == 1) ? g_Kp : g_Vp);
    const float* bias = (which == 0) ? bq : ((which == 1) ? bk : bv);

    float c[4][4][4];
    #pragma unroll
    for (int i = 0; i < 4; ++i)
        #pragma unroll
        for (int j = 0; j < 4; ++j)
            #pragma unroll
            for (int k = 0; k < 4; ++k) c[i][j][k] = 0.0f;

    gemm_mainloop(sm, A, EE, B, EE, EE / BK, tid, c, wr, wc, lane);
    gemm_epilogue(c, Cmat + (size_t)rowT * 128 * KK, KK, colT * 128,
                  0, bias, wr, wc, lane);
}

__constant__ int PT[10] = {0, 1, 1, 2, 2, 2, 3, 3, 3, 3};
__constant__ int PS[10] = {0, 0, 1, 0, 1, 2, 0, 1, 2, 3};

__global__ __launch_bounds__(256) void qkt_mma() {
    __shared__ SmemT sm;
    const int tid = threadIdx.x, lane = tid & 31, wid = tid >> 5;
    const int wr = wid >> 2, wc = wid & 3;
    const int tT = PT[blockIdx.x], sT = PS[blockIdx.x], b = blockIdx.y;

    const float* A = g_Q  + (size_t)b * TT * KK + (size_t)tT * 128 * KK;
    const float* B = g_Kp + (size_t)b * TT * KK + (size_t)sT * 128 * KK;

    float c[4][4][4];
    #pragma unroll
    for (int i = 0; i < 4; ++i)
        #pragma unroll
        for (int j = 0; j < 4; ++j)
            #pragma unroll
            for (int k = 0; k < 4; ++k) c[i][j][k] = 0.0f;

    gemm_mainloop(sm, A, KK, B, KK, KK / BK, tid, c, wr, wc, lane);
    gemm_epilogue(c, g_S + (size_t)b * TT * TT + (size_t)tT * 128 * TT, TT,
                  sT * 128, 1, nullptr, wr, wc, lane);
}

__global__ __launch_bounds__(256) void av_mma(float* __restrict__ out) {
    __shared__ SmemT sm;
    const int tid = threadIdx.x, lane = tid & 31, wid = tid >> 5;
    const int wr = wid >> 2, wc = wid & 3;
    const int vT = blockIdx.x, tT = blockIdx.y, b = blockIdx.z;

    const float* A = g_S  + (size_t)b * TT * TT + (size_t)tT * 128 * TT;
    const float* B = g_Vt + (size_t)b * TT * VV + (size_t)vT * 128 * TT;
    const int nc = (tT + 1) * (128 / BK);   // causal K cutoff

    float c[4][4][4];
    #pragma unroll
    for (int i = 0; i < 4; ++i)
        #pragma unroll
        for (int j = 0; j < 4; ++j)
            #pragma unroll
            for (int k = 0; k < 4; ++k) c[i][j][k] = 0.0f;

    gemm_mainloop(sm, A, TT, B, TT, nc, tid, c, wr, wc, lane);
    gemm_epilogue(c, out + (size_t)b * TT * VV + (size_t)tT * 128 * VV, VV,
                  vT * 128, 3, nullptr, wr, wc, lane);
}

// ---------------------------------------------------------------------------
// Aux kernels
// ---------------------------------------------------------------------------
__global__ __launch_bounds__(256) void roundx_kernel(const float* __restrict__ x) {
    size_t i = ((size_t)blockIdx.x * 256 + threadIdx.x) * 4;
    float4 v = *(const float4*)(x + i);
    v.x = rna_tf32(v.x); v.y = rna_tf32(v.y);
    v.z = rna_tf32(v.z); v.w = rna_tf32(v.w);
    *(float4*)(g_x + i) = v;
}

__global__ __launch_bounds__(256) void wtrans_kernel(const float* __restrict__ Wq,
                                                     const float* __restrict__ Wk,
                                                     const float* __restrict__ Wv) {
    __shared__ float t[32][33];
    const int which = blockIdx.z;
    const float* W = (which == 0) ? Wq : ((which == 1) ? Wk : Wv);
    float* WT = g_WT + (size_t)which * EE * KK;
    const int bx = blockIdx.x * 32, by = blockIdx.y * 32;
    #pragma unroll
    for (int j = 0; j < 32; j += 8)
        t[threadIdx.y + j][threadIdx.x] =
            W[(size_t)(by + threadIdx.y + j) * KK + bx + threadIdx.x];
    __syncthreads();
    #pragma unroll
    for (int j = 0; j < 32; j += 8)
        WT[(size_t)(bx + threadIdx.y + j) * EE + by + threadIdx.x] =
            rna_tf32(t[threadIdx.x][threadIdx.y + j]);
}

__global__ __launch_bounds__(256) void vtrans_kernel() {
    __shared__ float t[32][33];
    const int b = blockIdx.z;
    const float* V = g_Vp + (size_t)b * TT * VV;
    float* Vt = g_Vt + (size_t)b * TT * VV;
    const int bx = blockIdx.x * 32, by = blockIdx.y * 32;
    #pragma unroll
    for (int j = 0; j < 32; j += 8)
        t[threadIdx.y + j][threadIdx.x] =
            V[(size_t)(by + threadIdx.y + j) * VV + bx + threadIdx.x];
    __syncthreads();
    #pragma unroll
    for (int j = 0; j < 32; j += 8)
        Vt[(size_t)(bx + threadIdx.y + j) * TT + by + threadIdx.x] =
            rna_tf32(t[threadIdx.x][threadIdx.y + j]);
}

// Column softmax (axis = query/t). One thread per column s.
__global__ __launch_bounds__(128) void softmax_kernel() {
    const int b = blockIdx.y;
    const int s = blockIdx.x * 128 + threadIdx.x;
    float* Sb = g_S + (size_t)b * TT * TT;
    const int tile0 = blockIdx.x * 128;
    const int w0 = tile0 + (threadIdx.x & ~31);

    float m = -1e30f;
    #pragma unroll 4
    for (int t = w0; t < TT; ++t) {
        float xv = Sb[(size_t)t * TT + s];
        if (t >= s) m = fmaxf(m, xv);
    }
    float sum = 0.0f;
    #pragma unroll 4
    for (int t = w0; t < TT; ++t) {
        float xv = Sb[(size_t)t * TT + s];
        if (t >= s) sum += __expf(xv - m);
    }
    const float inv = 1.0f / sum;
    #pragma unroll 4
    for (int t = tile0; t < TT; ++t) {
        float xv = Sb[(size_t)t * TT + s];
        Sb[(size_t)t * TT + s] = (t >= s) ? rna_tf32(__expf(xv - m) * inv) : 0.0f;
    }
}

// ---------------------------------------------------------------------------
extern "C" void kernel_launch(void* const* d_in, const int* in_sizes, int n_in,
                              void* d_out, int out_size) {
    const float* x  = (const float*)d_in[0];
    const float* Wq = (const float*)d_in[1];
    const float* bq = (const float*)d_in[2];
    const float* Wk = (const float*)d_in[3];
    const float* bk = (const float*)d_in[4];
    const float* Wv = (const float*)d_in[5];
    const float* bv = (const float*)d_in[6];
    float* out = (float*)d_out;

    roundx_kernel<<<(NB * TT * EE) / (256 * 4), 256>>>(x);
    wtrans_kernel<<<dim3(16, 16, 3), dim3(32, 8)>>>(Wq, Wk, Wv);
    proj_mma<<<dim3(4, 256, 3), 256>>>(bq, bk, bv);
    vtrans_kernel<<<dim3(16, 16, 64), dim3(32, 8)>>>();
    qkt_mma<<<dim3(10, 64), 256>>>();
    softmax_kernel<<<dim3(4, 64), 128>>>();
    av_mma<<<dim3(4, 4, 64), 256>>>(out);
}

// round 4
// speedup vs baseline: 3.6270x; 1.5276x over previous
#include <cuda_runtime.h>
#include <cuda_fp16.h>
#include <cstdint>
#include <math.h>

#define NB 64
#define TT 512
#define EE 512
#define KK 512
#define VV 512
#define BKH 32                // K-elements (halves) per chunk
#define SMS 40                // smem row stride in halves (32 + 8 pad)

// ---------------------------------------------------------------------------
// Device scratch (allocation-free)
// ---------------------------------------------------------------------------
__device__ __half g_xh [(size_t)NB * TT * EE];   // x as fp16
__device__ __half g_WTh[(size_t)3 * EE * KK];    // W^T (N,K row-major) fp16
__device__ __half g_Qh [(size_t)NB * TT * KK];
__device__ __half g_Kh [(size_t)NB * TT * KK];
__device__ __half g_Vh [(size_t)NB * TT * VV];   // V [t][v] fp16
__device__ __half g_Vth[(size_t)NB * TT * VV];   // V^T [v][t] fp16
__device__ float  g_S  [(size_t)NB * TT * TT];   // scores fp32
__device__ __half g_Sh [(size_t)NB * TT * TT];   // attn fp16

// ---------------------------------------------------------------------------
// Helpers
// ---------------------------------------------------------------------------
__device__ __forceinline__ uint32_t smem_u32(const void* p) {
    uint32_t a;
    asm("{ .reg .u64 t; cvta.to.shared.u64 t, %1; cvt.u32.u64 %0, t; }"
        : "=r"(a) : "l"(p));
    return a;
}

#define CP_ASYNC16(dst, src) \
    asm volatile("cp.async.cg.shared.global [%0], [%1], 16;" \
                 :: "r"(dst), "l"(src) : "memory")
#define CP_COMMIT() asm volatile("cp.async.commit_group;" ::: "memory")
#define CP_WAIT0()  asm volatile("cp.async.wait_group 0;" ::: "memory")

#define LDSM_X4(r0, r1, r2, r3, addr)                                   \
    asm volatile("ldmatrix.sync.aligned.m8n8.x4.shared.b16 "            \
                 "{%0,%1,%2,%3}, [%4];"                                 \
                 : "=r"(r0), "=r"(r1), "=r"(r2), "=r"(r3) : "r"(addr))

// m16n8k16 fp16 MMA, fp32 accumulate
__device__ __forceinline__ void mma_f16(float* c, const uint32_t* a,
                                        const uint32_t* b) {
    asm volatile(
        "mma.sync.aligned.m16n8k16.row.col.f32.f16.f16.f32 "
        "{%0,%1,%2,%3}, {%4,%5,%6,%7}, {%8,%9}, {%0,%1,%2,%3};"
        : "+f"(c[0]), "+f"(c[1]), "+f"(c[2]), "+f"(c[3])
        : "r"(a[0]), "r"(a[1]), "r"(a[2]), "r"(a[3]), "r"(b[0]), "r"(b[1]));
}

// ---------------------------------------------------------------------------
// Shared tiles: [128 rows][SMS halves]; 80B row stride -> conflict-free
// for both cp.async 16B fills and ldmatrix 8-row phases.
// ---------------------------------------------------------------------------
struct __align__(16) SmemT {
    __half A[2][128][SMS];
    __half B[2][128][SMS];
};   // 2*2*128*40*2 = 40960 bytes

// Fill 128 x 32-half tile (row-major gmem, leading dim ldh halves)
__device__ __forceinline__ void load_tile(__half (*dst)[SMS],
                                          const __half* __restrict__ gsrc,
                                          int ldh, int tid) {
    unsigned long long gb = (unsigned long long)__cvta_generic_to_global(gsrc);
    #pragma unroll
    for (int i = 0; i < 2; ++i) {
        int ch  = i * 256 + tid;        // 0..511 chunks of 16B
        int row = ch >> 2;
        int off = ch & 3;
        uint32_t d = smem_u32(&dst[row][off * 8]);
        unsigned long long s = gb + (unsigned long long)row * ((size_t)ldh * 2)
                                  + (unsigned)off * 16;
        CP_ASYNC16(d, s);
    }
}

// One BKH=32 chunk: 2 k16-steps x (4 mt x 4 nt) MMAs per warp (64x32 tile)
__device__ __forceinline__ void compute_chunk(const __half (*As)[SMS],
                                              const __half (*Bs)[SMS],
                                              float c[4][4][4],
                                              int wr, int wc, int lane) {
    const int arow = lane & 15;
    const int asel = (lane >> 4) * 8;            // +0 / +8 in k
    const int bn   = (lane & 7) + ((lane >> 4) << 3);
    const int bsel = ((lane >> 3) & 1) * 8;      // +0 / +8 in k
    #pragma unroll
    for (int ks = 0; ks < 2; ++ks) {
        const int kh = ks * 16;
        uint32_t a[4][4], b[4][2];
        #pragma unroll
        for (int mt = 0; mt < 4; ++mt) {
            uint32_t ad = smem_u32(&As[wr * 64 + mt * 16 + arow][kh + asel]);
            LDSM_X4(a[mt][0], a[mt][1], a[mt][2], a[mt][3], ad);
        }
        #pragma unroll
        for (int np = 0; np < 2; ++np) {
            uint32_t r0, r1, r2, r3;
            uint32_t ad = smem_u32(&Bs[wc * 32 + np * 16 + bn][kh + bsel]);
            LDSM_X4(r0, r1, r2, r3, ad);
            b[np * 2][0] = r0; b[np * 2][1] = r1;
            b[np * 2 + 1][0] = r2; b[np * 2 + 1][1] = r3;
        }
        #pragma unroll
        for (int mt = 0; mt < 4; ++mt)
            #pragma unroll
            for (int nt = 0; nt < 4; ++nt)
                mma_f16(c[mt][nt], a[mt], b[nt]);
    }
}

// Mainloop: C128x128 += A[128,K] . B[128,K]^T, nc chunks of BKH halves.
// Single __syncthreads per chunk; next loads issued after the sync.
__device__ __forceinline__ void gemm_mainloop(SmemT& sm,
                                              const __half* __restrict__ A, int lda,
                                              const __half* __restrict__ B, int ldb,
                                              int nc, int tid,
                                              float c[4][4][4],
                                              int wr, int wc, int lane) {
    load_tile(sm.A[0], A, lda, tid);
    load_tile(sm.B[0], B, ldb, tid);
    CP_COMMIT();

    for (int ch = 0; ch < nc; ++ch) {
        const int buf = ch & 1;
        CP_WAIT0();
        __syncthreads();
        if (ch + 1 < nc) {
            load_tile(sm.A[1 - buf], A + (size_t)(ch + 1) * BKH, lda, tid);
            load_tile(sm.B[1 - buf], B + (size_t)(ch + 1) * BKH, ldb, tid);
            CP_COMMIT();
        }
        compute_chunk(sm.A[buf], sm.B[buf], c, wr, wc, lane);
    }
}

__device__ __forceinline__ void zero_acc(float c[4][4][4]) {
    #pragma unroll
    for (int i = 0; i < 4; ++i)
        #pragma unroll
        for (int j = 0; j < 4; ++j)
            #pragma unroll
            for (int k = 0; k < 4; ++k) c[i][j][k] = 0.0f;
}

// ---------------------------------------------------------------------------
// GEMM kernels
// ---------------------------------------------------------------------------
// Projections: out = x @ W + b -> fp16
__global__ __launch_bounds__(256) void proj_mma(const float* __restrict__ bq,
                                                const float* __restrict__ bk,
                                                const float* __restrict__ bv) {
    __shared__ SmemT sm;
    const int tid = threadIdx.x, lane = tid & 31, wid = tid >> 5;
    const int wr = wid >> 2, wc = wid & 3;
    const int colT = blockIdx.x, rowT = blockIdx.y, which = blockIdx.z;

    const __half* A = g_xh + (size_t)rowT * 128 * EE;
    const __half* B = g_WTh + (size_t)which * EE * KK + (size_t)colT * 128 * EE;
    __half* Cmat = (which == 0) ? g_Qh : ((which == 1) ? g_Kh : g_Vh);
    const float* bias = (which == 0) ? bq : ((which == 1) ? bk : bv);

    float c[4][4][4];
    zero_acc(c);
    gemm_mainloop(sm, A, EE, B, EE, EE / BKH, tid, c, wr, wc, lane);

    __half* Crow = Cmat + (size_t)rowT * 128 * KK;
    const int g = lane >> 2, q = lane & 3;
    #pragma unroll
    for (int mt = 0; mt < 4; ++mt) {
        #pragma unroll
        for (int nt = 0; nt < 4; ++nt) {
            const int row = wr * 64 + mt * 16 + g;
            const int col = colT * 128 + wc * 32 + nt * 8 + q * 2;
            float b0 = __ldg(bias + col), b1 = __ldg(bias + col + 1);
            *(__half2*)&Crow[(size_t)row * KK + col] =
                __floats2half2_rn(c[mt][nt][0] + b0, c[mt][nt][1] + b1);
            *(__half2*)&Crow[(size_t)(row + 8) * KK + col] =
                __floats2half2_rn(c[mt][nt][2] + b0, c[mt][nt][3] + b1);
        }
    }
}

__constant__ int PT[10] = {0, 1, 1, 2, 2, 2, 3, 3, 3, 3};
__constant__ int PS[10] = {0, 0, 1, 0, 1, 2, 0, 1, 2, 3};

// Scores: S = scale * Q K^T -> fp32 (only lower-triangular tiles)
__global__ __launch_bounds__(256) void qkt_mma() {
    __shared__ SmemT sm;
    const int tid = threadIdx.x, lane = tid & 31, wid = tid >> 5;
    const int wr = wid >> 2, wc = wid & 3;
    const int tT = PT[blockIdx.x], sT = PS[blockIdx.x], b = blockIdx.y;

    const __half* A = g_Qh + (size_t)b * TT * KK + (size_t)tT * 128 * KK;
    const __half* B = g_Kh + (size_t)b * TT * KK + (size_t)sT * 128 * KK;

    float c[4][4][4];
    zero_acc(c);
    gemm_mainloop(sm, A, KK, B, KK, KK / BKH, tid, c, wr, wc, lane);

    const float SCALE = 0.04419417382415922f;   // 1/sqrt(512)
    float* Crow = g_S + (size_t)b * TT * TT + (size_t)tT * 128 * TT;
    const int g = lane >> 2, q = lane & 3;
    #pragma unroll
    for (int mt = 0; mt < 4; ++mt) {
        #pragma unroll
        for (int nt = 0; nt < 4; ++nt) {
            const int row = wr * 64 + mt * 16 + g;
            const int col = sT * 128 + wc * 32 + nt * 8 + q * 2;
            *(float2*)&Crow[(size_t)row * TT + col] =
                make_float2(c[mt][nt][0] * SCALE, c[mt][nt][1] * SCALE);
            *(float2*)&Crow[(size_t)(row + 8) * TT + col] =
                make_float2(c[mt][nt][2] * SCALE, c[mt][nt][3] * SCALE);
        }
    }
}

// Output: out = attn @ V -> fp32, causal K cutoff
__global__ __launch_bounds__(256) void av_mma(float* __restrict__ out) {
    __shared__ SmemT sm;
    const int tid = threadIdx.x, lane = tid & 31, wid = tid >> 5;
    const int wr = wid >> 2, wc = wid & 3;
    const int vT = blockIdx.x, tT = blockIdx.y, b = blockIdx.z;

    const __half* A = g_Sh  + (size_t)b * TT * TT + (size_t)tT * 128 * TT;
    const __half* B = g_Vth + (size_t)b * TT * VV + (size_t)vT * 128 * TT;
    const int nc = (tT + 1) * (128 / BKH);

    float c[4][4][4];
    zero_acc(c);
    gemm_mainloop(sm, A, TT, B, TT, nc, tid, c, wr, wc, lane);

    float* Crow = out + (size_t)b * TT * VV + (size_t)tT * 128 * VV;
    const int g = lane >> 2, q = lane & 3;
    #pragma unroll
    for (int mt = 0; mt < 4; ++mt) {
        #pragma unroll
        for (int nt = 0; nt < 4; ++nt) {
            const int row = wr * 64 + mt * 16 + g;
            const int col = vT * 128 + wc * 32 + nt * 8 + q * 2;
            *(float2*)&Crow[(size_t)row * VV + col] =
                make_float2(c[mt][nt][0], c[mt][nt][1]);
            *(float2*)&Crow[(size_t)(row + 8) * VV + col] =
                make_float2(c[mt][nt][2], c[mt][nt][3]);
        }
    }
}

// ---------------------------------------------------------------------------
// Aux kernels
// ---------------------------------------------------------------------------
__global__ __launch_bounds__(256) void convx_kernel(const float* __restrict__ x) {
    size_t i = ((size_t)blockIdx.x * 256 + threadIdx.x) * 4;
    float4 v = *(const float4*)(x + i);
    __half2* d = (__half2*)(g_xh + i);
    d[0] = __floats2half2_rn(v.x, v.y);
    d[1] = __floats2half2_rn(v.z, v.w);
}

__global__ __launch_bounds__(256) void wtrans_kernel(const float* __restrict__ Wq,
                                                     const float* __restrict__ Wk,
                                                     const float* __restrict__ Wv) {
    __shared__ float t[32][33];
    const int which = blockIdx.z;
    const float* W = (which == 0) ? Wq : ((which == 1) ? Wk : Wv);
    __half* WT = g_WTh + (size_t)which * EE * KK;
    const int bx = blockIdx.x * 32, by = blockIdx.y * 32;
    #pragma unroll
    for (int j = 0; j < 32; j += 8)
        t[threadIdx.y + j][threadIdx.x] =
            W[(size_t)(by + threadIdx.y + j) * KK + bx + threadIdx.x];
    __syncthreads();
    #pragma unroll
    for (int j = 0; j < 32; j += 8)
        WT[(size_t)(bx + threadIdx.y + j) * EE + by + threadIdx.x] =
            __float2half(t[threadIdx.x][threadIdx.y + j]);
}

__global__ __launch_bounds__(256) void vtrans_kernel() {
    __shared__ __half t[32][34];
    const int b = blockIdx.z;
    const __half* V = g_Vh + (size_t)b * TT * VV;
    __half* Vt = g_Vth + (size_t)b * TT * VV;
    const int bx = blockIdx.x * 32, by = blockIdx.y * 32;
    #pragma unroll
    for (int j = 0; j < 32; j += 8)
        t[threadIdx.y + j][threadIdx.x] =
            V[(size_t)(by + threadIdx.y + j) * VV + bx + threadIdx.x];
    __syncthreads();
    #pragma unroll
    for (int j = 0; j < 32; j += 8)
        Vt[(size_t)(bx + threadIdx.y + j) * TT + by + threadIdx.x] =
            t[threadIdx.x][threadIdx.y + j];
}

// Column softmax (axis = query/t). One thread per column s; fp32 in, fp16 out.
__global__ __launch_bounds__(128) void softmax_kernel() {
    const int b = blockIdx.y;
    const int s = blockIdx.x * 128 + threadIdx.x;
    const float* Sb = g_S + (size_t)b * TT * TT;
    __half* Sh = g_Sh + (size_t)b * TT * TT;
    const int tile0 = blockIdx.x * 128;
    const int w0 = tile0 + (threadIdx.x & ~31);

    float m = -1e30f;
    #pragma unroll 4
    for (int t = w0; t < TT; ++t) {
        float xv = Sb[(size_t)t * TT + s];
        if (t >= s) m = fmaxf(m, xv);
    }
    float sum = 0.0f;
    #pragma unroll 4
    for (int t = w0; t < TT; ++t) {
        float xv = Sb[(size_t)t * TT + s];
        if (t >= s) sum += __expf(xv - m);
    }
    const float inv = 1.0f / sum;
    #pragma unroll 4
    for (int t = tile0; t < TT; ++t) {
        float xv = Sb[(size_t)t * TT + s];
        Sh[(size_t)t * TT + s] =
            (t >= s) ? __float2half(__expf(xv - m) * inv) : __half(0.0f);
    }
}

// ---------------------------------------------------------------------------
extern "C" void kernel_launch(void* const* d_in, const int* in_sizes, int n_in,
                              void* d_out, int out_size) {
    const float* x  = (const float*)d_in[0];
    const float* Wq = (const float*)d_in[1];
    const float* bq = (const float*)d_in[2];
    const float* Wk = (const float*)d_in[3];
    const float* bk = (const float*)d_in[4];
    const float* Wv = (const float*)d_in[5];
    const float* bv = (const float*)d_in[6];
    float* out = (float*)d_out;

    convx_kernel <<<(NB * TT * EE) / (256 * 4), 256>>>(x);
    wtrans_kernel<<<dim3(16, 16, 3), dim3(32, 8)>>>(Wq, Wk, Wv);
    proj_mma     <<<dim3(4, 256, 3), 256>>>(bq, bk, bv);
    vtrans_kernel<<<dim3(16, 16, 64), dim3(32, 8)>>>();
    qkt_mma      <<<dim3(10, 64), 256>>>();
    softmax_kernel<<<dim3(4, 64), 128>>>();
    av_mma       <<<dim3(4, 4, 64), 256>>>(out);
}